// round 16
// baseline (speedup 1.0000x reference)
#include <cuda_runtime.h>
#include <cuda_bf16.h>
#include <cstdint>
#include <math.h>

// Problem constants
#define BB 256   // batch == N
#define NN 256   // feature vectors per sample
#define DD 1024  // feature dim
#define SS 1024  // state dim
#define NQ 4     // i-quarters for pipelining
#define IQ (BB / NQ)

// ----- device scratch (allocation-free rule: __device__ globals) -----
__device__ __align__(16) float g_A[BB * SS];            // state @ Q^T
__device__ __align__(16) float g_pmax[BB * BB * 16];    // partial max per 64-col slab
__device__ __align__(16) float g_psum[BB * BB * 16];    // partial sumexp
__device__ __align__(16) __nv_bfloat16 g_Mhi[BB * NN];
__device__ __align__(16) __nv_bfloat16 g_Mlo[BB * NN];
// FV split hi/lo, SAME layout as FV: [i][n][d]
__device__ __align__(16) __nv_bfloat16 g_FVhi[(size_t)BB * NN * DD];
__device__ __align__(16) __nv_bfloat16 g_FVlo[(size_t)BB * NN * DD];

// ===========================================================================
// helpers
// ===========================================================================
static __device__ __forceinline__ uint32_t smem_u32(const void* p) {
    uint32_t a;
    asm("{ .reg .u64 t; cvta.to.shared.u64 t, %1; cvt.u32.u64 %0, t; }"
        : "=r"(a) : "l"(p));
    return a;
}
#define SWZ(x) ((x) ^ (((x) >> 3) & 0x70))

static __device__ __forceinline__ void cpasync16(uint32_t dst, const void* src) {
    asm volatile("cp.async.cg.shared.global [%0], [%1], 16;"
                 :: "r"(dst), "l"(src) : "memory");
}
static __device__ __forceinline__ void ldsm4(uint32_t* r, uint32_t a) {
    asm volatile("ldmatrix.sync.aligned.m8n8.x4.shared.b16 {%0,%1,%2,%3}, [%4];"
                 : "=r"(r[0]), "=r"(r[1]), "=r"(r[2]), "=r"(r[3]) : "r"(a));
}
static __device__ __forceinline__ void ldsm4t(uint32_t* r, uint32_t a) {
    asm volatile("ldmatrix.sync.aligned.m8n8.x4.trans.shared.b16 {%0,%1,%2,%3}, [%4];"
                 : "=r"(r[0]), "=r"(r[1]), "=r"(r[2]), "=r"(r[3]) : "r"(a));
}
static __device__ __forceinline__ void mma16816(float* c, const uint32_t* a,
                                                uint32_t b0, uint32_t b1) {
    asm volatile(
        "mma.sync.aligned.m16n8k16.row.col.f32.bf16.bf16.f32 "
        "{%0,%1,%2,%3}, {%4,%5,%6,%7}, {%8,%9}, {%0,%1,%2,%3};"
        : "+f"(c[0]), "+f"(c[1]), "+f"(c[2]), "+f"(c[3])
        : "r"(a[0]), "r"(a[1]), "r"(a[2]), "r"(a[3]), "r"(b0), "r"(b1));
}

struct __align__(8) bf16x4 { __nv_bfloat162 a, b; };

// ===========================================================================
// P1a: A[b,s] = sum_k state[b,k] * Q[s,k]
// ===========================================================================
__global__ __launch_bounds__(256) void gemm_state_qt(
    const float* __restrict__ state, const float* __restrict__ Q)
{
    __shared__ __align__(16) float As[16][64];
    __shared__ __align__(16) float Bs[16][64];
    const int tid = threadIdx.x;
    const int sBase = blockIdx.x * 64, bBase = blockIdx.y * 64;
    const int tx = tid & 15, ty = tid >> 4;
    const int r = tid >> 2, kk4 = (tid & 3) * 4;
    float acc[4][4] = {};
    for (int k0 = 0; k0 < SS; k0 += 16) {
        float4 va = *(const float4*)&state[(size_t)(bBase + r) * SS + k0 + kk4];
        float4 vb = *(const float4*)&Q[(size_t)(sBase + r) * SS + k0 + kk4];
        __syncthreads();
        As[kk4+0][r]=va.x; As[kk4+1][r]=va.y; As[kk4+2][r]=va.z; As[kk4+3][r]=va.w;
        Bs[kk4+0][r]=vb.x; Bs[kk4+1][r]=vb.y; Bs[kk4+2][r]=vb.z; Bs[kk4+3][r]=vb.w;
        __syncthreads();
        #pragma unroll
        for (int kk = 0; kk < 16; ++kk) {
            float4 a4 = *(const float4*)&As[kk][ty*4];
            float4 b4 = *(const float4*)&Bs[kk][tx*4];
            float a[4]={a4.x,a4.y,a4.z,a4.w}, b[4]={b4.x,b4.y,b4.z,b4.w};
            #pragma unroll
            for (int x=0;x<4;++x)
                #pragma unroll
                for (int y=0;y<4;++y) acc[x][y]=fmaf(a[x],b[y],acc[x][y]);
        }
    }
    #pragma unroll
    for (int x=0;x<4;++x) {
        float4 o={acc[x][0],acc[x][1],acc[x][2],acc[x][3]};
        *(float4*)&g_A[(size_t)(bBase+ty*4+x)*SS + sBase + tx*4] = o;
    }
}

// ===========================================================================
// P1b: M[b,n] = sum_s A[b,s] * K[s,n]  -> fused bf16 hi/lo split epilogue
// ===========================================================================
__global__ __launch_bounds__(256) void gemm_a_k(const float* __restrict__ Kmat)
{
    __shared__ __align__(16) float As[16][64];
    __shared__ __align__(16) float Bs[16][64];
    const int tid = threadIdx.x;
    const int nBase = blockIdx.x * 64, bBase = blockIdx.y * 64;
    const int tx = tid & 15, ty = tid >> 4;
    const int r = tid >> 2, kk4 = (tid & 3) * 4;
    const int kkb = tid >> 4, nn4 = (tid & 15) * 4;
    float acc[4][4] = {};
    for (int k0 = 0; k0 < SS; k0 += 16) {
        float4 va = *(const float4*)&g_A[(size_t)(bBase + r) * SS + k0 + kk4];
        float4 vb = *(const float4*)&Kmat[(size_t)(k0 + kkb) * NN + nBase + nn4];
        __syncthreads();
        As[kk4+0][r]=va.x; As[kk4+1][r]=va.y; As[kk4+2][r]=va.z; As[kk4+3][r]=va.w;
        *(float4*)&Bs[kkb][nn4] = vb;
        __syncthreads();
        #pragma unroll
        for (int kk = 0; kk < 16; ++kk) {
            float4 a4 = *(const float4*)&As[kk][ty*4];
            float4 b4 = *(const float4*)&Bs[kk][tx*4];
            float a[4]={a4.x,a4.y,a4.z,a4.w}, b[4]={b4.x,b4.y,b4.z,b4.w};
            #pragma unroll
            for (int x=0;x<4;++x)
                #pragma unroll
                for (int y=0;y<4;++y) acc[x][y]=fmaf(a[x],b[y],acc[x][y]);
        }
    }
    #pragma unroll
    for (int x=0;x<4;++x) {
        size_t idx = (size_t)(bBase+ty*4+x)*NN + nBase + tx*4;
        __nv_bfloat16 h0=__float2bfloat16(acc[x][0]);
        __nv_bfloat16 h1=__float2bfloat16(acc[x][1]);
        __nv_bfloat16 h2=__float2bfloat16(acc[x][2]);
        __nv_bfloat16 h3=__float2bfloat16(acc[x][3]);
        __nv_bfloat16 l0=__float2bfloat16(acc[x][0]-__bfloat162float(h0));
        __nv_bfloat16 l1=__float2bfloat16(acc[x][1]-__bfloat162float(h1));
        __nv_bfloat16 l2=__float2bfloat16(acc[x][2]-__bfloat162float(h2));
        __nv_bfloat16 l3=__float2bfloat16(acc[x][3]-__bfloat162float(h3));
        bf16x4 hv; hv.a=__nv_bfloat162(h0,h1); hv.b=__nv_bfloat162(h2,h3);
        bf16x4 lv; lv.a=__nv_bfloat162(l0,l1); lv.b=__nv_bfloat162(l2,l3);
        *(bf16x4*)&g_Mhi[idx] = hv;
        *(bf16x4*)&g_Mlo[idx] = lv;
    }
}

// ===========================================================================
// Split FV into bf16 hi/lo (same [i][n][d] layout), quarter of i-range.
// ===========================================================================
__global__ __launch_bounds__(256) void convert_fv(const float* __restrict__ FV,
                                                  size_t ebase)
{
    size_t idx = ebase + ((size_t)blockIdx.x * 256 + threadIdx.x) * 4;
    float4 v = *(const float4*)(FV + idx);
    __nv_bfloat16 h0 = __float2bfloat16(v.x);
    __nv_bfloat16 h1 = __float2bfloat16(v.y);
    __nv_bfloat16 h2 = __float2bfloat16(v.z);
    __nv_bfloat16 h3 = __float2bfloat16(v.w);
    __nv_bfloat16 l0 = __float2bfloat16(v.x - __bfloat162float(h0));
    __nv_bfloat16 l1 = __float2bfloat16(v.y - __bfloat162float(h1));
    __nv_bfloat16 l2 = __float2bfloat16(v.z - __bfloat162float(h2));
    __nv_bfloat16 l3 = __float2bfloat16(v.w - __bfloat162float(h3));
    bf16x4 hv; hv.a = __nv_bfloat162(h0, h1); hv.b = __nv_bfloat162(h2, h3);
    bf16x4 lv; lv.a = __nv_bfloat162(l0, l1); lv.b = __nv_bfloat162(l2, l3);
    *(bf16x4*)(g_FVhi + idx) = hv;
    *(bf16x4*)(g_FVlo + idx) = lv;
}

// ===========================================================================
// P2: logits via warp-level bf16 mma.sync, 3-term split, fp32 register accum.
// CTA: 256 thr (8 warps as 4b x 2d), tile 128(b) x 128(d).
// K=256 as 8 chunks of 32, 3-stage cp.async pipeline, ONE sync per chunk.
// 3 stages x 32KB = 96KB -> 2 CTAs/SM. Quarter of i handled per launch.
// ===========================================================================
#define LOGITS_SMEM (3 * 32768)
#define NCHUNK 8

__global__ __launch_bounds__(256, 2) void logits_mma(float* __restrict__ L,
                                                     int ibase)
{
    extern __shared__ char dsm[];
    const uint32_t sb = smem_u32(dsm);
    const int tid = threadIdx.x, lane = tid & 31, wid = tid >> 5;
    const int bwarp = wid >> 1, dwarp = wid & 1;
    const int dBase = blockIdx.x * 128, bBase = blockIdx.y * 128;
    const int i = ibase + blockIdx.z;

    float acc[2][8][4] = {};

    auto load_chunk = [&](int s, int stg) {
        const int k0 = s * 32;
        const uint32_t A0 = sb + stg * 32768;
        const uint32_t Bh = A0 + 16384, Bl = A0 + 24576;
        #pragma unroll
        for (int j = 0; j < 2; ++j) {
            int v = tid + j * 256, row = v >> 2, c = v & 3;
            size_t gi = (size_t)(bBase + row) * NN + k0 + c * 8;
            cpasync16(A0 + SWZ((uint32_t)(row * 128 + c * 16)), g_Mhi + gi);
            cpasync16(A0 + SWZ((uint32_t)(row * 128 + 64 + c * 16)), g_Mlo + gi);
        }
        #pragma unroll
        for (int j = 0; j < 2; ++j) {
            int v = tid + j * 256, row = v >> 4, c = v & 15;
            uint32_t off = (uint32_t)(row * 256 + (c ^ (row & 7)) * 16);
            size_t gi = ((size_t)i * NN + k0 + row) * DD + dBase + c * 8;
            cpasync16(Bh + off, g_FVhi + gi);
            cpasync16(Bl + off, g_FVlo + gi);
        }
        asm volatile("cp.async.commit_group;" ::: "memory");
    };

    auto compute_chunk = [&](int stg) {
        const uint32_t A0 = sb + stg * 32768;
        const uint32_t Bh = A0 + 16384, Bl = A0 + 24576;
        #pragma unroll
        for (int kk = 0; kk < 2; ++kk) {
            uint32_t ah[2][4], al[2][4];
            #pragma unroll
            for (int m = 0; m < 2; ++m) {
                int r = bwarp * 32 + m * 16 + (lane & 15);
                uint32_t base = (uint32_t)(r * 128 + kk * 32 + (lane >> 4) * 16);
                ldsm4(ah[m], A0 + SWZ(base));
                ldsm4(al[m], A0 + SWZ(base + 64));
            }
            #pragma unroll
            for (int g = 0; g < 4; ++g) {
                int r = kk * 16 + (lane & 15);
                int d = dwarp * 64 + g * 16 + (lane >> 4) * 8;
                uint32_t off = (uint32_t)(r * 256 + (((d >> 3) ^ (r & 7)) * 16));
                uint32_t bh[4], bl[4];
                ldsm4t(bh, Bh + off);
                ldsm4t(bl, Bl + off);
                #pragma unroll
                for (int m = 0; m < 2; ++m) {
                    mma16816(acc[m][2*g],   ah[m], bh[0], bh[1]);
                    mma16816(acc[m][2*g+1], ah[m], bh[2], bh[3]);
                    mma16816(acc[m][2*g],   ah[m], bl[0], bl[1]);
                    mma16816(acc[m][2*g+1], ah[m], bl[2], bl[3]);
                    mma16816(acc[m][2*g],   al[m], bh[0], bh[1]);
                    mma16816(acc[m][2*g+1], al[m], bh[2], bh[3]);
                }
            }
        }
    };

    load_chunk(0, 0);
    load_chunk(1, 1);
    #pragma unroll
    for (int s = 0; s < NCHUNK; ++s) {
        if (s < NCHUNK - 1)
            asm volatile("cp.async.wait_group 1;" ::: "memory");
        else
            asm volatile("cp.async.wait_group 0;" ::: "memory");
        __syncthreads();
        compute_chunk(s % 3);
        if (s + 2 < NCHUNK) load_chunk(s + 2, (s + 2) % 3);
    }

    // -------- epilogue: fused partial softmax stats + coalesced L stores ----
    const int r4 = lane >> 2, c2 = (lane & 3) * 2;
    const int slab = blockIdx.x * 2 + dwarp;  // 16 slabs of 64 d-cols

    #pragma unroll
    for (int m = 0; m < 2; ++m) {
        #pragma unroll
        for (int h = 0; h < 2; ++h) {
            const int row = bBase + bwarp * 32 + m * 16 + h * 8 + r4;
            float mx = -3.4e38f;
            #pragma unroll
            for (int nt = 0; nt < 8; ++nt)
                mx = fmaxf(mx, fmaxf(acc[m][nt][2*h], acc[m][nt][2*h+1]));
            float sum = 0.f;
            #pragma unroll
            for (int nt = 0; nt < 8; ++nt)
                sum += __expf(acc[m][nt][2*h] - mx) + __expf(acc[m][nt][2*h+1] - mx);
            #pragma unroll
            for (int o = 1; o < 4; o <<= 1) {
                float m2 = __shfl_xor_sync(0xffffffffu, mx, o);
                float s2 = __shfl_xor_sync(0xffffffffu, sum, o);
                float Mx = fmaxf(mx, m2);
                sum = sum * __expf(mx - Mx) + s2 * __expf(m2 - Mx);
                mx = Mx;
            }
            if ((lane & 3) == 0) {
                int prow = i * BB + row;
                g_pmax[prow * 16 + slab] = mx;
                g_psum[prow * 16 + slab] = sum;
            }
            const size_t ob = ((size_t)i * BB + row) * DD + dBase + dwarp * 64 + c2;
            #pragma unroll
            for (int nt = 0; nt < 8; ++nt) {
                float2 v = {acc[m][nt][2*h], acc[m][nt][2*h+1]};
                *(float2*)(L + ob + nt * 8) = v;
            }
        }
    }
}

// ===========================================================================
// P4: finalize (merge fused). Thread t merges 16 partials for row (i,t),
// then W = exp(L - max)*inv (in place), ctx = sum_b W * FV.
// ===========================================================================
__global__ __launch_bounds__(256) void finalize_kernel(
    float* __restrict__ W, const float* __restrict__ FV, float* __restrict__ ctx,
    int ibase)
{
    const int i = ibase + blockIdx.x;
    const int t = threadIdx.x;
    __shared__ float smax[256];
    __shared__ float sinv[256];
    {
        const int r = i * BB + t;
        float M = -3.4e38f;
        float pm[16];
        #pragma unroll
        for (int j = 0; j < 16; ++j) { pm[j] = g_pmax[r * 16 + j]; M = fmaxf(M, pm[j]); }
        float S = 0.f;
        #pragma unroll
        for (int j = 0; j < 16; ++j) S += g_psum[r * 16 + j] * __expf(pm[j] - M);
        smax[t] = M;
        sinv[t] = 1.f / S;
    }
    __syncthreads();

    const size_t base = (size_t)i * BB * DD + (size_t)t * 4;
    float cx = 0.f, cy = 0.f, cz = 0.f, cw = 0.f;

    #pragma unroll 4
    for (int b = 0; b < BB; ++b) {
        const size_t off = base + (size_t)b * DD;
        float4 l = *(const float4*)(W + off);
        float4 f = *(const float4*)(FV + off);
        const float m = smax[b], iv = sinv[b];
        float4 w;
        w.x = __expf(l.x - m) * iv;
        w.y = __expf(l.y - m) * iv;
        w.z = __expf(l.z - m) * iv;
        w.w = __expf(l.w - m) * iv;
        *(float4*)(W + off) = w;
        cx = fmaf(w.x, f.x, cx);
        cy = fmaf(w.y, f.y, cy);
        cz = fmaf(w.z, f.z, cz);
        cw = fmaf(w.w, f.w, cw);
    }
    float4 o = {cx, cy, cz, cw};
    *(float4*)(ctx + (size_t)i * DD + (size_t)t * 4) = o;
}

// ===========================================================================
// launch: fork-join multi-stream pipeline (graph-capture-safe pattern).
//   main (stream 0): gemm chain, logits quarters
//   side (s1):       convert_fv quarters, finalize quarters
// ===========================================================================
extern "C" void kernel_launch(void* const* d_in, const int* in_sizes, int n_in,
                              void* d_out, int out_size)
{
    (void)in_sizes; (void)n_in; (void)out_size;
    const float* FV    = (const float*)d_in[0];  // [256,256,1024]
    const float* state = (const float*)d_in[1];  // [256,1024]
    const float* Q     = (const float*)d_in[2];  // [1024,1024]
    const float* Kmat  = (const float*)d_in[3];  // [1024,256]

    float* ctx = (float*)d_out;                      // [256,1024]
    float* W   = (float*)d_out + (size_t)BB * DD;    // [256,256,1024]

    static cudaStream_t s1 = nullptr;
    static cudaEvent_t evFork, evC[NQ], evL[NQ], evFin;
    if (!s1) {
        cudaStreamCreateWithFlags(&s1, cudaStreamNonBlocking);
        cudaEventCreateWithFlags(&evFork, cudaEventDisableTiming);
        cudaEventCreateWithFlags(&evFin, cudaEventDisableTiming);
        for (int q = 0; q < NQ; ++q) {
            cudaEventCreateWithFlags(&evC[q], cudaEventDisableTiming);
            cudaEventCreateWithFlags(&evL[q], cudaEventDisableTiming);
        }
        cudaFuncSetAttribute(logits_mma,
                             cudaFuncAttributeMaxDynamicSharedMemorySize,
                             LOGITS_SMEM);
    }

    const size_t Q_ELEMS = (size_t)IQ * NN * DD;       // elems per quarter
    const int CONV_BLKS  = (int)(Q_ELEMS / 4 / 256);   // 16384

    // fork side stream off the capture/main stream
    cudaEventRecord(evFork, 0);
    cudaStreamWaitEvent(s1, evFork, 0);

    // side: FV split quarters
    for (int q = 0; q < NQ; ++q) {
        convert_fv<<<CONV_BLKS, 256, 0, s1>>>(FV, (size_t)q * Q_ELEMS);
        cudaEventRecord(evC[q], s1);
    }

    // main: M chain (independent of convert_fv)
    gemm_state_qt<<<dim3(SS / 64, BB / 64), 256>>>(state, Q);
    gemm_a_k     <<<dim3(NN / 64, BB / 64), 256>>>(Kmat);

    // main: logits quarters, each gated on its FV quarter
    for (int q = 0; q < NQ; ++q) {
        cudaStreamWaitEvent(0, evC[q], 0);
        logits_mma<<<dim3(DD / 128, BB / 128, IQ), 256, LOGITS_SMEM>>>(
            W, q * IQ);
        cudaEventRecord(evL[q], 0);
    }

    // side: finalize quarters, each gated on its logits quarter
    for (int q = 0; q < NQ; ++q) {
        cudaStreamWaitEvent(s1, evL[q], 0);
        finalize_kernel<<<IQ, 256, 0, s1>>>(W, FV, ctx, q * IQ);
    }

    // join side stream back into main
    cudaEventRecord(evFin, s1);
    cudaStreamWaitEvent(0, evFin, 0);
}

// round 17
// speedup vs baseline: 1.6035x; 1.6035x over previous
#include <cuda_runtime.h>
#include <cuda_bf16.h>
#include <cstdint>
#include <math.h>

// Problem constants
#define BB 256   // batch == N
#define NN 256   // feature vectors per sample
#define DD 1024  // feature dim
#define SS 1024  // state dim

// ----- device scratch (allocation-free rule: __device__ globals) -----
__device__ __align__(16) float g_A[BB * SS];            // state @ Q^T
__device__ __align__(16) float g_pmax[BB * BB * 16];    // partial max per 64-col slab
__device__ __align__(16) float g_psum[BB * BB * 16];    // partial sumexp
__device__ __align__(16) __nv_bfloat16 g_Mhi[BB * NN];
__device__ __align__(16) __nv_bfloat16 g_Mlo[BB * NN];
// FV split hi/lo, SAME layout as FV: [i][n][d]
__device__ __align__(16) __nv_bfloat16 g_FVhi[(size_t)BB * NN * DD];
__device__ __align__(16) __nv_bfloat16 g_FVlo[(size_t)BB * NN * DD];

// ===========================================================================
// helpers
// ===========================================================================
static __device__ __forceinline__ uint32_t smem_u32(const void* p) {
    uint32_t a;
    asm("{ .reg .u64 t; cvta.to.shared.u64 t, %1; cvt.u32.u64 %0, t; }"
        : "=r"(a) : "l"(p));
    return a;
}
#define SWZ(x) ((x) ^ (((x) >> 3) & 0x70))

static __device__ __forceinline__ void cpasync16(uint32_t dst, const void* src) {
    asm volatile("cp.async.cg.shared.global [%0], [%1], 16;"
                 :: "r"(dst), "l"(src) : "memory");
}
static __device__ __forceinline__ void ldsm4(uint32_t* r, uint32_t a) {
    asm volatile("ldmatrix.sync.aligned.m8n8.x4.shared.b16 {%0,%1,%2,%3}, [%4];"
                 : "=r"(r[0]), "=r"(r[1]), "=r"(r[2]), "=r"(r[3]) : "r"(a));
}
static __device__ __forceinline__ void ldsm4t(uint32_t* r, uint32_t a) {
    asm volatile("ldmatrix.sync.aligned.m8n8.x4.trans.shared.b16 {%0,%1,%2,%3}, [%4];"
                 : "=r"(r[0]), "=r"(r[1]), "=r"(r[2]), "=r"(r[3]) : "r"(a));
}
static __device__ __forceinline__ void mma16816(float* c, const uint32_t* a,
                                                uint32_t b0, uint32_t b1) {
    asm volatile(
        "mma.sync.aligned.m16n8k16.row.col.f32.bf16.bf16.f32 "
        "{%0,%1,%2,%3}, {%4,%5,%6,%7}, {%8,%9}, {%0,%1,%2,%3};"
        : "+f"(c[0]), "+f"(c[1]), "+f"(c[2]), "+f"(c[3])
        : "r"(a[0]), "r"(a[1]), "r"(a[2]), "r"(a[3]), "r"(b0), "r"(b1));
}

struct __align__(8) bf16x4 { __nv_bfloat162 a, b; };

// ===========================================================================
// P1a: A[b,s] = sum_k state[b,k] * Q[s,k]
// ===========================================================================
__global__ __launch_bounds__(256) void gemm_state_qt(
    const float* __restrict__ state, const float* __restrict__ Q)
{
    __shared__ __align__(16) float As[16][64];
    __shared__ __align__(16) float Bs[16][64];
    const int tid = threadIdx.x;
    const int sBase = blockIdx.x * 64, bBase = blockIdx.y * 64;
    const int tx = tid & 15, ty = tid >> 4;
    const int r = tid >> 2, kk4 = (tid & 3) * 4;
    float acc[4][4] = {};
    for (int k0 = 0; k0 < SS; k0 += 16) {
        float4 va = *(const float4*)&state[(size_t)(bBase + r) * SS + k0 + kk4];
        float4 vb = *(const float4*)&Q[(size_t)(sBase + r) * SS + k0 + kk4];
        __syncthreads();
        As[kk4+0][r]=va.x; As[kk4+1][r]=va.y; As[kk4+2][r]=va.z; As[kk4+3][r]=va.w;
        Bs[kk4+0][r]=vb.x; Bs[kk4+1][r]=vb.y; Bs[kk4+2][r]=vb.z; Bs[kk4+3][r]=vb.w;
        __syncthreads();
        #pragma unroll
        for (int kk = 0; kk < 16; ++kk) {
            float4 a4 = *(const float4*)&As[kk][ty*4];
            float4 b4 = *(const float4*)&Bs[kk][tx*4];
            float a[4]={a4.x,a4.y,a4.z,a4.w}, b[4]={b4.x,b4.y,b4.z,b4.w};
            #pragma unroll
            for (int x=0;x<4;++x)
                #pragma unroll
                for (int y=0;y<4;++y) acc[x][y]=fmaf(a[x],b[y],acc[x][y]);
        }
    }
    #pragma unroll
    for (int x=0;x<4;++x) {
        float4 o={acc[x][0],acc[x][1],acc[x][2],acc[x][3]};
        *(float4*)&g_A[(size_t)(bBase+ty*4+x)*SS + sBase + tx*4] = o;
    }
}

// ===========================================================================
// P1b: M[b,n] = sum_s A[b,s] * K[s,n]  -> fused bf16 hi/lo split epilogue
// ===========================================================================
__global__ __launch_bounds__(256) void gemm_a_k(const float* __restrict__ Kmat)
{
    __shared__ __align__(16) float As[16][64];
    __shared__ __align__(16) float Bs[16][64];
    const int tid = threadIdx.x;
    const int nBase = blockIdx.x * 64, bBase = blockIdx.y * 64;
    const int tx = tid & 15, ty = tid >> 4;
    const int r = tid >> 2, kk4 = (tid & 3) * 4;
    const int kkb = tid >> 4, nn4 = (tid & 15) * 4;
    float acc[4][4] = {};
    for (int k0 = 0; k0 < SS; k0 += 16) {
        float4 va = *(const float4*)&g_A[(size_t)(bBase + r) * SS + k0 + kk4];
        float4 vb = *(const float4*)&Kmat[(size_t)(k0 + kkb) * NN + nBase + nn4];
        __syncthreads();
        As[kk4+0][r]=va.x; As[kk4+1][r]=va.y; As[kk4+2][r]=va.z; As[kk4+3][r]=va.w;
        *(float4*)&Bs[kkb][nn4] = vb;
        __syncthreads();
        #pragma unroll
        for (int kk = 0; kk < 16; ++kk) {
            float4 a4 = *(const float4*)&As[kk][ty*4];
            float4 b4 = *(const float4*)&Bs[kk][tx*4];
            float a[4]={a4.x,a4.y,a4.z,a4.w}, b[4]={b4.x,b4.y,b4.z,b4.w};
            #pragma unroll
            for (int x=0;x<4;++x)
                #pragma unroll
                for (int y=0;y<4;++y) acc[x][y]=fmaf(a[x],b[y],acc[x][y]);
        }
    }
    #pragma unroll
    for (int x=0;x<4;++x) {
        size_t idx = (size_t)(bBase+ty*4+x)*NN + nBase + tx*4;
        __nv_bfloat16 h0=__float2bfloat16(acc[x][0]);
        __nv_bfloat16 h1=__float2bfloat16(acc[x][1]);
        __nv_bfloat16 h2=__float2bfloat16(acc[x][2]);
        __nv_bfloat16 h3=__float2bfloat16(acc[x][3]);
        __nv_bfloat16 l0=__float2bfloat16(acc[x][0]-__bfloat162float(h0));
        __nv_bfloat16 l1=__float2bfloat16(acc[x][1]-__bfloat162float(h1));
        __nv_bfloat16 l2=__float2bfloat16(acc[x][2]-__bfloat162float(h2));
        __nv_bfloat16 l3=__float2bfloat16(acc[x][3]-__bfloat162float(h3));
        bf16x4 hv; hv.a=__nv_bfloat162(h0,h1); hv.b=__nv_bfloat162(h2,h3);
        bf16x4 lv; lv.a=__nv_bfloat162(l0,l1); lv.b=__nv_bfloat162(l2,l3);
        *(bf16x4*)&g_Mhi[idx] = hv;
        *(bf16x4*)&g_Mlo[idx] = lv;
    }
}

// ===========================================================================
// Split FV into bf16 hi/lo (same [i][n][d] layout)
// ===========================================================================
__global__ __launch_bounds__(256) void convert_fv(const float* __restrict__ FV)
{
    size_t idx = ((size_t)blockIdx.x * 256 + threadIdx.x) * 4;
    float4 v = *(const float4*)(FV + idx);
    __nv_bfloat16 h0 = __float2bfloat16(v.x);
    __nv_bfloat16 h1 = __float2bfloat16(v.y);
    __nv_bfloat16 h2 = __float2bfloat16(v.z);
    __nv_bfloat16 h3 = __float2bfloat16(v.w);
    __nv_bfloat16 l0 = __float2bfloat16(v.x - __bfloat162float(h0));
    __nv_bfloat16 l1 = __float2bfloat16(v.y - __bfloat162float(h1));
    __nv_bfloat16 l2 = __float2bfloat16(v.z - __bfloat162float(h2));
    __nv_bfloat16 l3 = __float2bfloat16(v.w - __bfloat162float(h3));
    bf16x4 hv; hv.a = __nv_bfloat162(h0, h1); hv.b = __nv_bfloat162(h2, h3);
    bf16x4 lv; lv.a = __nv_bfloat162(l0, l1); lv.b = __nv_bfloat162(l2, l3);
    *(bf16x4*)(g_FVhi + idx) = hv;
    *(bf16x4*)(g_FVlo + idx) = lv;
}

// ===========================================================================
// P2: logits via warp-level bf16 mma.sync, 3-term split, fp32 register accum.
// CTA: 256 thr (8 warps as 4b x 2d), tile 128(b) x 128(d).
// K=256 as 8 chunks of 32, 3-stage cp.async pipeline, ONE sync per chunk.
// 3 stages x 32KB = 96KB -> 2 CTAs/SM.
// Epilogue: slab-wide max first, then stores P = exp(v - slab_max) (so
// finalize needs no per-element exp), plus per-slab (max, sumexp).
// ===========================================================================
#define LOGITS_SMEM (3 * 32768)
#define NCHUNK 8

__global__ __launch_bounds__(256, 2) void logits_mma(float* __restrict__ L)
{
    extern __shared__ char dsm[];
    const uint32_t sb = smem_u32(dsm);
    const int tid = threadIdx.x, lane = tid & 31, wid = tid >> 5;
    const int bwarp = wid >> 1, dwarp = wid & 1;
    const int dBase = blockIdx.x * 128, bBase = blockIdx.y * 128;
    const int i = blockIdx.z;

    float acc[2][8][4] = {};

    auto load_chunk = [&](int s, int stg) {
        const int k0 = s * 32;
        const uint32_t A0 = sb + stg * 32768;
        const uint32_t Bh = A0 + 16384, Bl = A0 + 24576;
        #pragma unroll
        for (int j = 0; j < 2; ++j) {
            int v = tid + j * 256, row = v >> 2, c = v & 3;
            size_t gi = (size_t)(bBase + row) * NN + k0 + c * 8;
            cpasync16(A0 + SWZ((uint32_t)(row * 128 + c * 16)), g_Mhi + gi);
            cpasync16(A0 + SWZ((uint32_t)(row * 128 + 64 + c * 16)), g_Mlo + gi);
        }
        #pragma unroll
        for (int j = 0; j < 2; ++j) {
            int v = tid + j * 256, row = v >> 4, c = v & 15;
            uint32_t off = (uint32_t)(row * 256 + (c ^ (row & 7)) * 16);
            size_t gi = ((size_t)i * NN + k0 + row) * DD + dBase + c * 8;
            cpasync16(Bh + off, g_FVhi + gi);
            cpasync16(Bl + off, g_FVlo + gi);
        }
        asm volatile("cp.async.commit_group;" ::: "memory");
    };

    auto compute_chunk = [&](int stg) {
        const uint32_t A0 = sb + stg * 32768;
        const uint32_t Bh = A0 + 16384, Bl = A0 + 24576;
        #pragma unroll
        for (int kk = 0; kk < 2; ++kk) {
            uint32_t ah[2][4], al[2][4];
            #pragma unroll
            for (int m = 0; m < 2; ++m) {
                int r = bwarp * 32 + m * 16 + (lane & 15);
                uint32_t base = (uint32_t)(r * 128 + kk * 32 + (lane >> 4) * 16);
                ldsm4(ah[m], A0 + SWZ(base));
                ldsm4(al[m], A0 + SWZ(base + 64));
            }
            #pragma unroll
            for (int g = 0; g < 4; ++g) {
                int r = kk * 16 + (lane & 15);
                int d = dwarp * 64 + g * 16 + (lane >> 4) * 8;
                uint32_t off = (uint32_t)(r * 256 + (((d >> 3) ^ (r & 7)) * 16));
                uint32_t bh[4], bl[4];
                ldsm4t(bh, Bh + off);
                ldsm4t(bl, Bl + off);
                #pragma unroll
                for (int m = 0; m < 2; ++m) {
                    mma16816(acc[m][2*g],   ah[m], bh[0], bh[1]);
                    mma16816(acc[m][2*g+1], ah[m], bh[2], bh[3]);
                    mma16816(acc[m][2*g],   ah[m], bl[0], bl[1]);
                    mma16816(acc[m][2*g+1], ah[m], bl[2], bl[3]);
                    mma16816(acc[m][2*g],   al[m], bh[0], bh[1]);
                    mma16816(acc[m][2*g+1], al[m], bh[2], bh[3]);
                }
            }
        }
    };

    load_chunk(0, 0);
    load_chunk(1, 1);
    #pragma unroll
    for (int s = 0; s < NCHUNK; ++s) {
        if (s < NCHUNK - 1)
            asm volatile("cp.async.wait_group 1;" ::: "memory");
        else
            asm volatile("cp.async.wait_group 0;" ::: "memory");
        __syncthreads();
        compute_chunk(s % 3);
        if (s + 2 < NCHUNK) load_chunk(s + 2, (s + 2) % 3);
    }

    // ---- epilogue: slab max -> exp store + per-slab (max, sumexp) ---------
    const int r4 = lane >> 2, c2 = (lane & 3) * 2;
    const int slab = blockIdx.x * 2 + dwarp;  // 16 slabs of 64 d-cols

    #pragma unroll
    for (int m = 0; m < 2; ++m) {
        #pragma unroll
        for (int h = 0; h < 2; ++h) {
            const int row = bBase + bwarp * 32 + m * 16 + h * 8 + r4;
            // slab-wide max FIRST (4 lanes share this row)
            float mx = -3.4e38f;
            #pragma unroll
            for (int nt = 0; nt < 8; ++nt)
                mx = fmaxf(mx, fmaxf(acc[m][nt][2*h], acc[m][nt][2*h+1]));
            #pragma unroll
            for (int o = 1; o < 4; o <<= 1)
                mx = fmaxf(mx, __shfl_xor_sync(0xffffffffu, mx, o));
            // exp in place, accumulate sum
            float sum = 0.f;
            #pragma unroll
            for (int nt = 0; nt < 8; ++nt) {
                float e0 = __expf(acc[m][nt][2*h]   - mx);
                float e1 = __expf(acc[m][nt][2*h+1] - mx);
                acc[m][nt][2*h]   = e0;
                acc[m][nt][2*h+1] = e1;
                sum += e0 + e1;
            }
            #pragma unroll
            for (int o = 1; o < 4; o <<= 1)
                sum += __shfl_xor_sync(0xffffffffu, sum, o);
            if ((lane & 3) == 0) {
                int prow = i * BB + row;
                g_pmax[prow * 16 + slab] = mx;
                g_psum[prow * 16 + slab] = sum;
            }
            const size_t ob = ((size_t)i * BB + row) * DD + dBase + dwarp * 64 + c2;
            #pragma unroll
            for (int nt = 0; nt < 8; ++nt) {
                float2 v = {acc[m][nt][2*h], acc[m][nt][2*h+1]};
                *(float2*)(L + ob + nt * 8) = v;
            }
        }
    }
}

// ===========================================================================
// P4: finalize. Block builds scale table f[b][slab] = exp(pm - M)/S once
// (merge fused), then W = P * f[b][slab] in place, ctx = sum_b W * FV.
// No per-element exp -> purely DRAM-bound.
// ===========================================================================
__global__ __launch_bounds__(256) void finalize_kernel(
    float* __restrict__ W, const float* __restrict__ FV, float* __restrict__ ctx)
{
    const int i = blockIdx.x;
    const int t = threadIdx.x;
    __shared__ float sf[256][16];   // 16KB scale table
    {
        const int r = i * BB + t;
        float pm[16];
        float M = -3.4e38f;
        #pragma unroll
        for (int j = 0; j < 16; ++j) { pm[j] = g_pmax[r * 16 + j]; M = fmaxf(M, pm[j]); }
        float S = 0.f;
        #pragma unroll
        for (int j = 0; j < 16; ++j) S += g_psum[r * 16 + j] * __expf(pm[j] - M);
        const float inv = 1.f / S;
        #pragma unroll
        for (int j = 0; j < 16; ++j) sf[t][j] = __expf(pm[j] - M) * inv;
    }
    __syncthreads();

    const int slab = t >> 4;        // d = t*4..t*4+3 lies in slab t/16
    const size_t base = (size_t)i * BB * DD + (size_t)t * 4;
    float cx = 0.f, cy = 0.f, cz = 0.f, cw = 0.f;

    #pragma unroll 4
    for (int b = 0; b < BB; ++b) {
        const size_t off = base + (size_t)b * DD;
        float4 p = *(const float4*)(W + off);
        float4 f = *(const float4*)(FV + off);
        const float sc = sf[b][slab];
        float4 w;
        w.x = p.x * sc;
        w.y = p.y * sc;
        w.z = p.z * sc;
        w.w = p.w * sc;
        *(float4*)(W + off) = w;
        cx = fmaf(w.x, f.x, cx);
        cy = fmaf(w.y, f.y, cy);
        cz = fmaf(w.z, f.z, cz);
        cw = fmaf(w.w, f.w, cw);
    }
    float4 o = {cx, cy, cz, cw};
    *(float4*)(ctx + (size_t)i * DD + (size_t)t * 4) = o;
}

// ===========================================================================
// launch (single stream — R16 multi-stream overlap regressed, reverted)
// ===========================================================================
extern "C" void kernel_launch(void* const* d_in, const int* in_sizes, int n_in,
                              void* d_out, int out_size)
{
    (void)in_sizes; (void)n_in; (void)out_size;
    const float* FV    = (const float*)d_in[0];  // [256,256,1024]
    const float* state = (const float*)d_in[1];  // [256,1024]
    const float* Q     = (const float*)d_in[2];  // [1024,1024]
    const float* Kmat  = (const float*)d_in[3];  // [1024,256]

    float* ctx = (float*)d_out;                      // [256,1024]
    float* W   = (float*)d_out + (size_t)BB * DD;    // [256,256,1024]

    cudaFuncSetAttribute(logits_mma, cudaFuncAttributeMaxDynamicSharedMemorySize,
                         LOGITS_SMEM);

    gemm_state_qt<<<dim3(SS / 64, BB / 64), 256>>>(state, Q);
    gemm_a_k     <<<dim3(NN / 64, BB / 64), 256>>>(Kmat);
    convert_fv   <<<(int)(((size_t)BB * NN * DD) / 4 / 256), 256>>>(FV);
    logits_mma   <<<dim3(DD / 128, BB / 128, BB), 256, LOGITS_SMEM>>>(W);
    finalize_kernel<<<BB, 256>>>(W, FV, ctx);
}